// round 6
// baseline (speedup 1.0000x reference)
#include <cuda_runtime.h>
#include <cuda_fp16.h>

#define NPTS  50000
#define BATCH 8
#define PTILE 64
#define NTILES_PER_B ((NPTS + PTILE - 1) / PTILE)   /* 782 */
#define NTILES (BATCH * NTILES_PER_B)               /* 6256 */
#define THREADS 512
#define GRID 296

/* ---- SMEM word/float offsets (4B units) ---- */
#define Z1H_W   0        /* z1 fp16x2: [64 pt][stride 68 words] */
#define Z1STRW  68
#define Z2F     4352     /* z2 fp32 [64 pt][stride 132] */
#define Z2STR   132
#define OUTWF   12800
#define H2BF    13184
#define G2BF    13312
#define OUTBF   13440
#define X0F     13444
#define XCF     13636
#define K1F     13828
#define K2F     14020
#define KSF     14212
#define SMEM_FLOATS 14404
#define SMEM_BYTES  (SMEM_FLOATS * 4)

/* A fragments fp16: [gemm(2)][mstrip(8)][kstep(8)][lane(32)] int4 */
__device__ int4 d_Afrag[4096];

__device__ __forceinline__ unsigned hpack(float a, float b) {
    __half2 h = __floats2half2_rn(a, b);
    return *(unsigned*)&h;
}
__device__ __forceinline__ float fast_sigmoid(float x) {
    float e = __expf(-x);
    return __fdividef(1.0f, 1.0f + e);
}
__device__ __forceinline__ float fast_tanh(float x) {
    float e = __expf(2.0f * x);
    return 1.0f - __fdividef(2.0f, e + 1.0f);
}
__device__ __forceinline__ void mma16816(float* d, const int4 a,
                                         unsigned b0, unsigned b1) {
    asm volatile(
        "mma.sync.aligned.m16n8k16.row.col.f32.f16.f16.f32 "
        "{%0,%1,%2,%3}, {%4,%5,%6,%7}, {%8,%9}, {%0,%1,%2,%3};"
        : "+f"(d[0]), "+f"(d[1]), "+f"(d[2]), "+f"(d[3])
        : "r"(a.x), "r"(a.y), "r"(a.z), "r"(a.w), "r"(b0), "r"(b1));
}

/* ---------- prep: per-lane fp16 A fragments from h2_w/g2_w ---------- */
__global__ void prep_kernel(const float* __restrict__ h2w,
                            const float* __restrict__ g2w)
{
    int j = blockIdx.x * blockDim.x + threadIdx.x;
    if (j >= 4096) return;
    int lane = j & 31;
    int k    = (j >> 5) & 7;
    int m    = (j >> 8) & 7;
    int gemm = (j >> 11) & 1;
    int g = lane >> 2, tq = lane & 3;
    int r0 = m * 16 + g, r1 = r0 + 8;
    int c0 = k * 16 + 2 * tq, c2 = c0 + 8;
    const float* src = gemm ? g2w : h2w;
    int4 f;
    f.x = (int)hpack(src[r0 * 128 + c0], src[r0 * 128 + c0 + 1]);
    f.y = (int)hpack(src[r1 * 128 + c0], src[r1 * 128 + c0 + 1]);
    f.z = (int)hpack(src[r0 * 128 + c2], src[r0 * 128 + c2 + 1]);
    f.w = (int)hpack(src[r1 * 128 + c2], src[r1 * 128 + c2 + 1]);
    d_Afrag[j] = f;
}

extern __shared__ float smf[];

__global__ __launch_bounds__(THREADS, 2)
void node_kernel(const float* __restrict__ x0g,
                 const float* __restrict__ h1w, const float* __restrict__ h1b,
                 const float* __restrict__ g1w, const float* __restrict__ g1b,
                 const float* __restrict__ h2b, const float* __restrict__ g2b,
                 const float* __restrict__ outw, const float* __restrict__ outb,
                 float* __restrict__ outg)
{
    const int t = threadIdx.x;
    const int wid = t >> 5, lane = t & 31;
    unsigned* smw = (unsigned*)smf;

    /* ---- one-time small weights into SMEM ---- */
    if (t < 128) {
        smf[H2BF + t] = h2b[t];
        smf[G2BF + t] = g2b[t];
    }
    for (int j = t; j < 384; j += THREADS) smf[OUTWF + j] = outw[j];
    if (t < 3) smf[OUTBF + t] = outb[t];

    /* per-warp GEMM constants: 16 warps = (m-strip 0..7) x (n-half 0..1) */
    const int m  = wid & 7;
    const int nh = wid >> 3;
    const int g = lane >> 2, tq = lane & 3;
    const int4* Ah = d_Afrag + ((0 * 8 + m) * 8) * 32 + lane;
    const int4* Ag = d_Afrag + ((1 * 8 + m) * 8) * 32 + lane;

    /* layer-1 mapping: (channel pair cp, point group pg of 8 pts) */
    const int cp = t & 63, pg = t >> 6;
    const int c0 = 2 * cp;
    /* out-pass mapping (t<192) */
    const int oc = t / 64, op = t - oc * 64;
    const float third = 1.0f / 3.0f;

    for (int tile = blockIdx.x; tile < NTILES; tile += gridDim.x)
    {
        const int b  = tile / NTILES_PER_B;
        const int n0 = (tile - b * NTILES_PER_B) * PTILE;

        __syncthreads();
        if (t < 192) {
            int n = n0 + op;
            float v = (n < NPTS) ? x0g[(size_t)b * 3 * NPTS + (size_t)oc * NPTS + n]
                                 : 0.0f;
            smf[X0F + t] = v;
            smf[XCF + t] = v;
        }
        __syncthreads();

        #pragma unroll
        for (int s = 0; s < 4; ++s)
        {
            const float ts = (s == 0) ? 0.0f : (s == 1) ? third
                           : (s == 2) ? 2.0f * third : 1.0f;

            /* ---------- layer 1: reg weights, 2 ch x 8 pts per thread ---------- */
            {
                float4 hwA = *(const float4*)&h1w[c0 * 4];
                float4 hwB = *(const float4*)&h1w[c0 * 4 + 4];
                float4 gwA = *(const float4*)&g1w[c0 * 4];
                float4 gwB = *(const float4*)&g1w[c0 * 4 + 4];
                float hbA = h1b[c0], hbB = h1b[c0 + 1];
                float gbA = g1b[c0], gbB = g1b[c0 + 1];
                int pt0 = pg * 8;
                #pragma unroll
                for (int i = 0; i < 8; ++i) {
                    int pt = pt0 + i;
                    float xa = smf[XCF + pt];
                    float xb = smf[XCF + 64 + pt];
                    float xc = smf[XCF + 128 + pt];
                    float hA = hbA + hwA.x * xa + hwA.y * xb + hwA.z * xc + hwA.w * ts;
                    float gA = gbA + gwA.x * xa + gwA.y * xb + gwA.z * xc + gwA.w * ts;
                    float hB = hbB + hwB.x * xa + hwB.y * xb + hwB.z * xc + hwB.w * ts;
                    float gB = gbB + gwB.x * xa + gwB.y * xb + gwB.z * xc + gwB.w * ts;
                    float z0 = fmaxf(hA * fast_sigmoid(gA), 0.0f);
                    float z1 = fmaxf(hB * fast_sigmoid(gB), 0.0f);
                    smw[Z1H_W + pt * Z1STRW + cp] = hpack(z0, z1);
                }
            }
            __syncthreads();

            /* ---------- layer 2: fp16 mma, single B plane, n-outer ---------- */
            {
                float hb0 = smf[H2BF + m * 16 + g], hb8 = smf[H2BF + m * 16 + g + 8];
                float gb0 = smf[G2BF + m * 16 + g], gb8 = smf[G2BF + m * 16 + g + 8];
                int ch0 = m * 16 + g;
                #pragma unroll
                for (int nn = 0; nn < 2; ++nn) {
                    const int n  = nh * 2 + nn;
                    const int nb = n * 16;
                    float ha[8] = {0, 0, 0, 0, 0, 0, 0, 0};
                    float ga[8] = {0, 0, 0, 0, 0, 0, 0, 0};
                    #pragma unroll
                    for (int k = 0; k < 8; ++k) {
                        int4 a_h = Ah[k * 32];
                        int4 a_g = Ag[k * 32];
                        int w0 = (nb + g) * Z1STRW + k * 8 + tq;
                        int w1 = w0 + 8 * Z1STRW;
                        unsigned b00 = smw[Z1H_W + w0], b01 = smw[Z1H_W + w0 + 4];
                        unsigned b10 = smw[Z1H_W + w1], b11 = smw[Z1H_W + w1 + 4];
                        mma16816(ha + 0, a_h, b00, b01);
                        mma16816(ha + 4, a_h, b10, b11);
                        mma16816(ga + 0, a_g, b00, b01);
                        mma16816(ga + 4, a_g, b10, b11);
                    }
                    /* GLU epilogue -> z2 fp32 */
                    #pragma unroll
                    for (int half = 0; half < 2; ++half) {
                        int ptb = nb + half * 8 + 2 * tq;
                        const float* hh = ha + half * 4;
                        const float* gg = ga + half * 4;
                        float v0 = fmaxf((hh[0] + hb0) * fast_sigmoid(gg[0] + gb0), 0.0f);
                        float v1 = fmaxf((hh[1] + hb0) * fast_sigmoid(gg[1] + gb0), 0.0f);
                        float v2 = fmaxf((hh[2] + hb8) * fast_sigmoid(gg[2] + gb8), 0.0f);
                        float v3 = fmaxf((hh[3] + hb8) * fast_sigmoid(gg[3] + gb8), 0.0f);
                        smf[Z2F + (ptb)     * Z2STR + ch0]     = v0;
                        smf[Z2F + (ptb + 1) * Z2STR + ch0]     = v1;
                        smf[Z2F + (ptb)     * Z2STR + ch0 + 8] = v2;
                        smf[Z2F + (ptb + 1) * Z2STR + ch0 + 8] = v3;
                    }
                }
            }
            __syncthreads();

            /* ---------- out layer (float4) + RK4 (192 threads) ---------- */
            if (t < 192) {
                const float4* wrow = (const float4*)&smf[OUTWF + oc * 128];
                const float4* zrow = (const float4*)&smf[Z2F + op * Z2STR];
                float a0 = 0.f, a1 = 0.f, a2 = 0.f, a3 = 0.f;
                #pragma unroll 8
                for (int i = 0; i < 32; ++i) {
                    float4 w4 = wrow[i];
                    float4 z4 = zrow[i];
                    a0 += w4.x * z4.x;
                    a1 += w4.y * z4.y;
                    a2 += w4.z * z4.z;
                    a3 += w4.w * z4.w;
                }
                float v  = smf[OUTBF + oc] + ((a0 + a1) + (a2 + a3));
                float kv = 0.5f * fast_tanh(v);
                float x0v = smf[X0F + t];
                if (s == 0) {
                    smf[KSF + t] = kv;
                    smf[K1F + t] = kv;
                    smf[XCF + t] = x0v + kv * third;
                } else if (s == 1) {
                    smf[KSF + t] += 3.0f * kv;
                    smf[K2F + t] = kv;
                    smf[XCF + t] = x0v + kv - smf[K1F + t] * third;
                } else if (s == 2) {
                    smf[KSF + t] += 3.0f * kv;
                    smf[XCF + t] = x0v + smf[K1F + t] - smf[K2F + t] + kv;
                } else {
                    float y = x0v + 0.125f * (smf[KSF + t] + kv);
                    int n = n0 + op;
                    if (n < NPTS)
                        outg[(size_t)b * 3 * NPTS + (size_t)oc * NPTS + n] = y;
                }
            }
            __syncthreads();
        } /* stages */
    } /* tiles */
}

extern "C" void kernel_launch(void* const* d_in, const int* in_sizes, int n_in,
                              void* d_out, int out_size)
{
    const float* x0   = (const float*)d_in[0];
    const float* h1w  = (const float*)d_in[1];
    const float* h1b  = (const float*)d_in[2];
    const float* g1w  = (const float*)d_in[3];
    const float* g1b  = (const float*)d_in[4];
    const float* h2w  = (const float*)d_in[5];
    const float* h2b  = (const float*)d_in[6];
    const float* g2w  = (const float*)d_in[7];
    const float* g2b  = (const float*)d_in[8];
    const float* outw = (const float*)d_in[9];
    const float* outb = (const float*)d_in[10];

    cudaFuncSetAttribute(node_kernel,
                         cudaFuncAttributeMaxDynamicSharedMemorySize, SMEM_BYTES);

    prep_kernel<<<16, 256>>>(h2w, g2w);
    node_kernel<<<GRID, THREADS, SMEM_BYTES>>>(x0, h1w, h1b, g1w, g1b,
                                               h2b, g2b, outw, outb,
                                               (float*)d_out);
}

// round 7
// speedup vs baseline: 1.9959x; 1.9959x over previous
#include <cuda_runtime.h>
#include <cuda_fp16.h>

#define NPTS  50000
#define BATCH 8
#define PTILE 64
#define NTILES_PER_B ((NPTS + PTILE - 1) / PTILE)   /* 782 */
#define NTILES (BATCH * NTILES_PER_B)               /* 6256 */
#define THREADS 256
#define GRID 296

/* ---- SMEM word/float offsets (4B units) ---- */
#define Z1H_W   0        /* z1 fp16x2: [64 pt][stride 68 words] */
#define Z1STRW  68
#define Z2F     4352     /* z2 fp32 [64 pt][stride 132] */
#define Z2STR   132
#define OUTWF   12800
#define H2BF    13184
#define G2BF    13312
#define OUTBF   13440
#define X0F     13444
#define XCF     13636
#define K1F     13828
#define K2F     14020
#define KSF     14212
#define SMEM_FLOATS 14404
#define SMEM_BYTES  (SMEM_FLOATS * 4)

/* A fragments fp16: [gemm(2)][mstrip(8)][kstep(8)][lane(32)] int4 */
__device__ int4 d_Afrag[4096];

__device__ __forceinline__ unsigned hpack(float a, float b) {
    __half2 h = __floats2half2_rn(a, b);
    return *(unsigned*)&h;
}
__device__ __forceinline__ float fast_sigmoid(float x) {
    float e = __expf(-x);
    return __fdividef(1.0f, 1.0f + e);
}
__device__ __forceinline__ float fast_tanh(float x) {
    float e = __expf(2.0f * x);
    return 1.0f - __fdividef(2.0f, e + 1.0f);
}
__device__ __forceinline__ void mma16816(float* d, const int4 a,
                                         unsigned b0, unsigned b1) {
    asm volatile(
        "mma.sync.aligned.m16n8k16.row.col.f32.f16.f16.f32 "
        "{%0,%1,%2,%3}, {%4,%5,%6,%7}, {%8,%9}, {%0,%1,%2,%3};"
        : "+f"(d[0]), "+f"(d[1]), "+f"(d[2]), "+f"(d[3])
        : "r"(a.x), "r"(a.y), "r"(a.z), "r"(a.w), "r"(b0), "r"(b1));
}

/* ---------- prep: per-lane fp16 A fragments from h2_w/g2_w ---------- */
__global__ void prep_kernel(const float* __restrict__ h2w,
                            const float* __restrict__ g2w)
{
    int j = blockIdx.x * blockDim.x + threadIdx.x;
    if (j >= 4096) return;
    int lane = j & 31;
    int k    = (j >> 5) & 7;
    int m    = (j >> 8) & 7;
    int gemm = (j >> 11) & 1;
    int g = lane >> 2, tq = lane & 3;
    int r0 = m * 16 + g, r1 = r0 + 8;
    int c0 = k * 16 + 2 * tq, c2 = c0 + 8;
    const float* src = gemm ? g2w : h2w;
    int4 f;
    f.x = (int)hpack(src[r0 * 128 + c0], src[r0 * 128 + c0 + 1]);
    f.y = (int)hpack(src[r1 * 128 + c0], src[r1 * 128 + c0 + 1]);
    f.z = (int)hpack(src[r0 * 128 + c2], src[r0 * 128 + c2 + 1]);
    f.w = (int)hpack(src[r1 * 128 + c2], src[r1 * 128 + c2 + 1]);
    d_Afrag[j] = f;
}

extern __shared__ float smf[];

__global__ __launch_bounds__(THREADS, 2)
void node_kernel(const float* __restrict__ x0g,
                 const float* __restrict__ h1w, const float* __restrict__ h1b,
                 const float* __restrict__ g1w, const float* __restrict__ g1b,
                 const float* __restrict__ h2b, const float* __restrict__ g2b,
                 const float* __restrict__ outw, const float* __restrict__ outb,
                 float* __restrict__ outg)
{
    const int t = threadIdx.x;
    const int wid = t >> 5, lane = t & 31;
    unsigned* smw = (unsigned*)smf;

    /* ---- one-time small weights into SMEM ---- */
    if (t < 128) {
        smf[H2BF + t] = h2b[t];
        smf[G2BF + t] = g2b[t];
    }
    for (int j = t; j < 384; j += THREADS) smf[OUTWF + j] = outw[j];
    if (t < 3) smf[OUTBF + t] = outb[t];

    /* per-warp GEMM constants (m-strip = wid), k-outer / n-inner */
    const int m = wid;
    const int g = lane >> 2, tq = lane & 3;
    const int4* Ah = d_Afrag + ((0 * 8 + m) * 8) * 32 + lane;
    const int4* Ag = d_Afrag + ((1 * 8 + m) * 8) * 32 + lane;

    /* layer-1 mapping: (channel pair cp, point group pg of 16 pts) */
    const int cp = t & 63, pg = t >> 6;
    const int c0 = 2 * cp;
    /* out-pass mapping (t<192) */
    const int oc = t / 64, op = t - oc * 64;
    const float third = 1.0f / 3.0f;

    for (int tile = blockIdx.x; tile < NTILES; tile += gridDim.x)
    {
        const int b  = tile / NTILES_PER_B;
        const int n0 = (tile - b * NTILES_PER_B) * PTILE;

        __syncthreads();
        if (t < 192) {
            int n = n0 + op;
            float v = (n < NPTS) ? x0g[(size_t)b * 3 * NPTS + (size_t)oc * NPTS + n]
                                 : 0.0f;
            smf[X0F + t] = v;
            smf[XCF + t] = v;
        }
        __syncthreads();

        #pragma unroll
        for (int s = 0; s < 4; ++s)
        {
            const float ts = (s == 0) ? 0.0f : (s == 1) ? third
                           : (s == 2) ? 2.0f * third : 1.0f;

            /* ---------- layer 1: reg weights, 2 ch x 16 pts per thread ---------- */
            {
                float4 hwA = *(const float4*)&h1w[c0 * 4];
                float4 hwB = *(const float4*)&h1w[c0 * 4 + 4];
                float4 gwA = *(const float4*)&g1w[c0 * 4];
                float4 gwB = *(const float4*)&g1w[c0 * 4 + 4];
                float hbA = h1b[c0], hbB = h1b[c0 + 1];
                float gbA = g1b[c0], gbB = g1b[c0 + 1];
                int pt0 = pg * 16;
                #pragma unroll 4
                for (int i = 0; i < 16; ++i) {
                    int pt = pt0 + i;
                    float xa = smf[XCF + pt];
                    float xb = smf[XCF + 64 + pt];
                    float xc = smf[XCF + 128 + pt];
                    float hA = hbA + hwA.x * xa + hwA.y * xb + hwA.z * xc + hwA.w * ts;
                    float gA = gbA + gwA.x * xa + gwA.y * xb + gwA.z * xc + gwA.w * ts;
                    float hB = hbB + hwB.x * xa + hwB.y * xb + hwB.z * xc + hwB.w * ts;
                    float gB = gbB + gwB.x * xa + gwB.y * xb + gwB.z * xc + gwB.w * ts;
                    float z0 = fmaxf(hA * fast_sigmoid(gA), 0.0f);
                    float z1 = fmaxf(hB * fast_sigmoid(gB), 0.0f);
                    smw[Z1H_W + pt * Z1STRW + cp] = hpack(z0, z1);
                }
            }
            __syncthreads();

            /* ---------- layer 2: fp16 mma, single B plane, k-outer / n-inner ---------- */
            {
                float ha[4][8], ga[4][8];
                #pragma unroll
                for (int n = 0; n < 4; ++n)
                    #pragma unroll
                    for (int j = 0; j < 8; ++j) { ha[n][j] = 0.f; ga[n][j] = 0.f; }

                #pragma unroll
                for (int k = 0; k < 8; ++k) {
                    int4 a_h = Ah[k * 32];
                    int4 a_g = Ag[k * 32];
                    #pragma unroll
                    for (int n = 0; n < 4; ++n) {
                        int w0 = (n * 16 + g) * Z1STRW + k * 8 + tq;
                        int w1 = w0 + 8 * Z1STRW;
                        unsigned b00 = smw[Z1H_W + w0], b01 = smw[Z1H_W + w0 + 4];
                        unsigned b10 = smw[Z1H_W + w1], b11 = smw[Z1H_W + w1 + 4];
                        mma16816(ha[n] + 0, a_h, b00, b01);
                        mma16816(ha[n] + 4, a_h, b10, b11);
                        mma16816(ga[n] + 0, a_g, b00, b01);
                        mma16816(ga[n] + 4, a_g, b10, b11);
                    }
                }

                /* GLU epilogue -> z2 fp32 [pt][132] */
                float hb0 = smf[H2BF + m * 16 + g], hb8 = smf[H2BF + m * 16 + g + 8];
                float gb0 = smf[G2BF + m * 16 + g], gb8 = smf[G2BF + m * 16 + g + 8];
                int ch0 = m * 16 + g;
                #pragma unroll
                for (int n = 0; n < 4; ++n) {
                    #pragma unroll
                    for (int half = 0; half < 2; ++half) {
                        int ptb = n * 16 + half * 8 + 2 * tq;
                        const float* hh = ha[n] + half * 4;
                        const float* gg = ga[n] + half * 4;
                        float v0 = fmaxf((hh[0] + hb0) * fast_sigmoid(gg[0] + gb0), 0.0f);
                        float v1 = fmaxf((hh[1] + hb0) * fast_sigmoid(gg[1] + gb0), 0.0f);
                        float v2 = fmaxf((hh[2] + hb8) * fast_sigmoid(gg[2] + gb8), 0.0f);
                        float v3 = fmaxf((hh[3] + hb8) * fast_sigmoid(gg[3] + gb8), 0.0f);
                        smf[Z2F + (ptb)     * Z2STR + ch0]     = v0;
                        smf[Z2F + (ptb + 1) * Z2STR + ch0]     = v1;
                        smf[Z2F + (ptb)     * Z2STR + ch0 + 8] = v2;
                        smf[Z2F + (ptb + 1) * Z2STR + ch0 + 8] = v3;
                    }
                }
            }
            __syncthreads();

            /* ---------- out layer (float4) + RK4 (192 threads) ---------- */
            if (t < 192) {
                const float4* wrow = (const float4*)&smf[OUTWF + oc * 128];
                const float4* zrow = (const float4*)&smf[Z2F + op * Z2STR];
                float a0 = 0.f, a1 = 0.f, a2 = 0.f, a3 = 0.f;
                #pragma unroll 8
                for (int i = 0; i < 32; ++i) {
                    float4 w4 = wrow[i];
                    float4 z4 = zrow[i];
                    a0 += w4.x * z4.x;
                    a1 += w4.y * z4.y;
                    a2 += w4.z * z4.z;
                    a3 += w4.w * z4.w;
                }
                float v  = smf[OUTBF + oc] + ((a0 + a1) + (a2 + a3));
                float kv = 0.5f * fast_tanh(v);
                float x0v = smf[X0F + t];
                if (s == 0) {
                    smf[KSF + t] = kv;
                    smf[K1F + t] = kv;
                    smf[XCF + t] = x0v + kv * third;
                } else if (s == 1) {
                    smf[KSF + t] += 3.0f * kv;
                    smf[K2F + t] = kv;
                    smf[XCF + t] = x0v + kv - smf[K1F + t] * third;
                } else if (s == 2) {
                    smf[KSF + t] += 3.0f * kv;
                    smf[XCF + t] = x0v + smf[K1F + t] - smf[K2F + t] + kv;
                } else {
                    float y = x0v + 0.125f * (smf[KSF + t] + kv);
                    int n = n0 + op;
                    if (n < NPTS)
                        outg[(size_t)b * 3 * NPTS + (size_t)oc * NPTS + n] = y;
                }
            }
            __syncthreads();
        } /* stages */
    } /* tiles */
}

extern "C" void kernel_launch(void* const* d_in, const int* in_sizes, int n_in,
                              void* d_out, int out_size)
{
    const float* x0   = (const float*)d_in[0];
    const float* h1w  = (const float*)d_in[1];
    const float* h1b  = (const float*)d_in[2];
    const float* g1w  = (const float*)d_in[3];
    const float* g1b  = (const float*)d_in[4];
    const float* h2w  = (const float*)d_in[5];
    const float* h2b  = (const float*)d_in[6];
    const float* g2w  = (const float*)d_in[7];
    const float* g2b  = (const float*)d_in[8];
    const float* outw = (const float*)d_in[9];
    const float* outb = (const float*)d_in[10];

    cudaFuncSetAttribute(node_kernel,
                         cudaFuncAttributeMaxDynamicSharedMemorySize, SMEM_BYTES);

    prep_kernel<<<16, 256>>>(h2w, g2w);
    node_kernel<<<GRID, THREADS, SMEM_BYTES>>>(x0, h1w, h1b, g1w, g1b,
                                               h2b, g2b, outw, outb,
                                               (float*)d_out);
}

// round 8
// speedup vs baseline: 2.2100x; 1.1073x over previous
#include <cuda_runtime.h>
#include <cuda_fp16.h>

#define NPTS  50000
#define BATCH 8
#define PTILE 64
#define NTILES_PER_B ((NPTS + PTILE - 1) / PTILE)   /* 782 */
#define NTILES (BATCH * NTILES_PER_B)               /* 6256 */
#define THREADS 256
#define GRID 296

/* ---- SMEM word/float offsets (4B units) ---- */
#define Z1H_W   0        /* z1 fp16x2: [64 pt][stride 68 words] */
#define Z1STRW  68
#define Z2F     4352     /* z2 fp32 [64 pt][stride 132] */
#define Z2STR   132
#define OUTWF   12800
#define H2BF    13184
#define G2BF    13312
#define OUTBF   13440
#define X0F     13444
#define XCF     13636
#define K1F     13828
#define K2F     14020
#define KSF     14212
#define SMEM_FLOATS 14404
#define SMEM_BYTES  (SMEM_FLOATS * 4)

/* A fragments fp16: [gemm(2)][mstrip(8)][kstep(8)][lane(32)] int4 */
__device__ int4 d_Afrag[4096];

__device__ __forceinline__ unsigned hpack(float a, float b) {
    __half2 h = __floats2half2_rn(a, b);
    return *(unsigned*)&h;
}
__device__ __forceinline__ float tanh_approx(float x) {
    float y;
    asm("tanh.approx.f32 %0, %1;" : "=f"(y) : "f"(x));
    return y;
}
__device__ __forceinline__ float fast_sigmoid(float x) {
    /* sigmoid(x) = 0.5*tanh(x/2) + 0.5 : 1 MUFU + FMA (vs EX2+RCP) */
    return fmaf(0.5f, tanh_approx(0.5f * x), 0.5f);
}
__device__ __forceinline__ float fast_tanh(float x) {
    return tanh_approx(x);
}
__device__ __forceinline__ void mma16816(float* d, const int4 a,
                                         unsigned b0, unsigned b1) {
    asm volatile(
        "mma.sync.aligned.m16n8k16.row.col.f32.f16.f16.f32 "
        "{%0,%1,%2,%3}, {%4,%5,%6,%7}, {%8,%9}, {%0,%1,%2,%3};"
        : "+f"(d[0]), "+f"(d[1]), "+f"(d[2]), "+f"(d[3])
        : "r"(a.x), "r"(a.y), "r"(a.z), "r"(a.w), "r"(b0), "r"(b1));
}

/* ---------- prep: per-lane fp16 A fragments from h2_w/g2_w ---------- */
__global__ void prep_kernel(const float* __restrict__ h2w,
                            const float* __restrict__ g2w)
{
    int j = blockIdx.x * blockDim.x + threadIdx.x;
    if (j >= 4096) return;
    int lane = j & 31;
    int k    = (j >> 5) & 7;
    int m    = (j >> 8) & 7;
    int gemm = (j >> 11) & 1;
    int g = lane >> 2, tq = lane & 3;
    int r0 = m * 16 + g, r1 = r0 + 8;
    int c0 = k * 16 + 2 * tq, c2 = c0 + 8;
    const float* src = gemm ? g2w : h2w;
    int4 f;
    f.x = (int)hpack(src[r0 * 128 + c0], src[r0 * 128 + c0 + 1]);
    f.y = (int)hpack(src[r1 * 128 + c0], src[r1 * 128 + c0 + 1]);
    f.z = (int)hpack(src[r0 * 128 + c2], src[r0 * 128 + c2 + 1]);
    f.w = (int)hpack(src[r1 * 128 + c2], src[r1 * 128 + c2 + 1]);
    d_Afrag[j] = f;
}

extern __shared__ float smf[];

__global__ __launch_bounds__(THREADS, 2)
void node_kernel(const float* __restrict__ x0g,
                 const float* __restrict__ h1w, const float* __restrict__ h1b,
                 const float* __restrict__ g1w, const float* __restrict__ g1b,
                 const float* __restrict__ h2b, const float* __restrict__ g2b,
                 const float* __restrict__ outw, const float* __restrict__ outb,
                 float* __restrict__ outg)
{
    const int t = threadIdx.x;
    const int wid = t >> 5, lane = t & 31;
    unsigned* smw = (unsigned*)smf;

    /* ---- one-time small weights into SMEM ---- */
    if (t < 128) {
        smf[H2BF + t] = h2b[t];
        smf[G2BF + t] = g2b[t];
    }
    for (int j = t; j < 384; j += THREADS) smf[OUTWF + j] = outw[j];
    if (t < 3) smf[OUTBF + t] = outb[t];

    /* per-warp GEMM constants (m-strip = wid), k-outer / n-inner */
    const int m = wid;
    const int g = lane >> 2, tq = lane & 3;
    const int4* Ah = d_Afrag + ((0 * 8 + m) * 8) * 32 + lane;
    const int4* Ag = d_Afrag + ((1 * 8 + m) * 8) * 32 + lane;

    /* layer-1 mapping: (channel pair cp, point group pg of 16 pts) */
    const int cp = t & 63, pg = t >> 6;
    const int c0 = 2 * cp;
    /* out-pass mapping (t<192) */
    const int oc = t / 64, op = t - oc * 64;
    const float third = 1.0f / 3.0f;

    for (int tile = blockIdx.x; tile < NTILES; tile += gridDim.x)
    {
        const int b  = tile / NTILES_PER_B;
        const int n0 = (tile - b * NTILES_PER_B) * PTILE;

        __syncthreads();
        if (t < 192) {
            int n = n0 + op;
            float v = (n < NPTS) ? x0g[(size_t)b * 3 * NPTS + (size_t)oc * NPTS + n]
                                 : 0.0f;
            smf[X0F + t] = v;
            smf[XCF + t] = v;
        }
        __syncthreads();

        #pragma unroll
        for (int s = 0; s < 4; ++s)
        {
            const float ts = (s == 0) ? 0.0f : (s == 1) ? third
                           : (s == 2) ? 2.0f * third : 1.0f;

            /* ---------- layer 1: reg weights, 2 ch x 16 pts per thread ---------- */
            {
                float4 hwA = *(const float4*)&h1w[c0 * 4];
                float4 hwB = *(const float4*)&h1w[c0 * 4 + 4];
                float4 gwA = *(const float4*)&g1w[c0 * 4];
                float4 gwB = *(const float4*)&g1w[c0 * 4 + 4];
                float hbA = h1b[c0], hbB = h1b[c0 + 1];
                float gbA = g1b[c0], gbB = g1b[c0 + 1];
                int pt0 = pg * 16;
                #pragma unroll 4
                for (int i = 0; i < 16; ++i) {
                    int pt = pt0 + i;
                    float xa = smf[XCF + pt];
                    float xb = smf[XCF + 64 + pt];
                    float xc = smf[XCF + 128 + pt];
                    float hA = hbA + hwA.x * xa + hwA.y * xb + hwA.z * xc + hwA.w * ts;
                    float gA = gbA + gwA.x * xa + gwA.y * xb + gwA.z * xc + gwA.w * ts;
                    float hB = hbB + hwB.x * xa + hwB.y * xb + hwB.z * xc + hwB.w * ts;
                    float gB = gbB + gwB.x * xa + gwB.y * xb + gwB.z * xc + gwB.w * ts;
                    float z0 = fmaxf(hA * fast_sigmoid(gA), 0.0f);
                    float z1 = fmaxf(hB * fast_sigmoid(gB), 0.0f);
                    smw[Z1H_W + pt * Z1STRW + cp] = hpack(z0, z1);
                }
            }
            __syncthreads();

            /* ---------- layer 2: fp16 mma, single B plane, k-outer / n-inner ---------- */
            {
                float ha[4][8], ga[4][8];
                #pragma unroll
                for (int n = 0; n < 4; ++n)
                    #pragma unroll
                    for (int j = 0; j < 8; ++j) { ha[n][j] = 0.f; ga[n][j] = 0.f; }

                #pragma unroll
                for (int k = 0; k < 8; ++k) {
                    int4 a_h = Ah[k * 32];
                    int4 a_g = Ag[k * 32];
                    #pragma unroll
                    for (int n = 0; n < 4; ++n) {
                        int w0 = (n * 16 + g) * Z1STRW + k * 8 + tq;
                        int w1 = w0 + 8 * Z1STRW;
                        unsigned b00 = smw[Z1H_W + w0], b01 = smw[Z1H_W + w0 + 4];
                        unsigned b10 = smw[Z1H_W + w1], b11 = smw[Z1H_W + w1 + 4];
                        mma16816(ha[n] + 0, a_h, b00, b01);
                        mma16816(ha[n] + 4, a_h, b10, b11);
                        mma16816(ga[n] + 0, a_g, b00, b01);
                        mma16816(ga[n] + 4, a_g, b10, b11);
                    }
                }

                /* GLU epilogue -> z2 fp32 [pt][132] */
                float hb0 = smf[H2BF + m * 16 + g], hb8 = smf[H2BF + m * 16 + g + 8];
                float gb0 = smf[G2BF + m * 16 + g], gb8 = smf[G2BF + m * 16 + g + 8];
                int ch0 = m * 16 + g;
                #pragma unroll
                for (int n = 0; n < 4; ++n) {
                    #pragma unroll
                    for (int half = 0; half < 2; ++half) {
                        int ptb = n * 16 + half * 8 + 2 * tq;
                        const float* hh = ha[n] + half * 4;
                        const float* gg = ga[n] + half * 4;
                        float v0 = fmaxf((hh[0] + hb0) * fast_sigmoid(gg[0] + gb0), 0.0f);
                        float v1 = fmaxf((hh[1] + hb0) * fast_sigmoid(gg[1] + gb0), 0.0f);
                        float v2 = fmaxf((hh[2] + hb8) * fast_sigmoid(gg[2] + gb8), 0.0f);
                        float v3 = fmaxf((hh[3] + hb8) * fast_sigmoid(gg[3] + gb8), 0.0f);
                        smf[Z2F + (ptb)     * Z2STR + ch0]     = v0;
                        smf[Z2F + (ptb + 1) * Z2STR + ch0]     = v1;
                        smf[Z2F + (ptb)     * Z2STR + ch0 + 8] = v2;
                        smf[Z2F + (ptb + 1) * Z2STR + ch0 + 8] = v3;
                    }
                }
            }
            __syncthreads();

            /* ---------- out layer (float4) + RK4 (192 threads) ---------- */
            if (t < 192) {
                const float4* wrow = (const float4*)&smf[OUTWF + oc * 128];
                const float4* zrow = (const float4*)&smf[Z2F + op * Z2STR];
                float a0 = 0.f, a1 = 0.f, a2 = 0.f, a3 = 0.f;
                #pragma unroll 8
                for (int i = 0; i < 32; ++i) {
                    float4 w4 = wrow[i];
                    float4 z4 = zrow[i];
                    a0 += w4.x * z4.x;
                    a1 += w4.y * z4.y;
                    a2 += w4.z * z4.z;
                    a3 += w4.w * z4.w;
                }
                float v  = smf[OUTBF + oc] + ((a0 + a1) + (a2 + a3));
                float kv = 0.5f * fast_tanh(v);
                float x0v = smf[X0F + t];
                if (s == 0) {
                    smf[KSF + t] = kv;
                    smf[K1F + t] = kv;
                    smf[XCF + t] = x0v + kv * third;
                } else if (s == 1) {
                    smf[KSF + t] += 3.0f * kv;
                    smf[K2F + t] = kv;
                    smf[XCF + t] = x0v + kv - smf[K1F + t] * third;
                } else if (s == 2) {
                    smf[KSF + t] += 3.0f * kv;
                    smf[XCF + t] = x0v + smf[K1F + t] - smf[K2F + t] + kv;
                } else {
                    float y = x0v + 0.125f * (smf[KSF + t] + kv);
                    int n = n0 + op;
                    if (n < NPTS)
                        outg[(size_t)b * 3 * NPTS + (size_t)oc * NPTS + n] = y;
                }
            }
            __syncthreads();
        } /* stages */
    } /* tiles */
}

extern "C" void kernel_launch(void* const* d_in, const int* in_sizes, int n_in,
                              void* d_out, int out_size)
{
    const float* x0   = (const float*)d_in[0];
    const float* h1w  = (const float*)d_in[1];
    const float* h1b  = (const float*)d_in[2];
    const float* g1w  = (const float*)d_in[3];
    const float* g1b  = (const float*)d_in[4];
    const float* h2w  = (const float*)d_in[5];
    const float* h2b  = (const float*)d_in[6];
    const float* g2w  = (const float*)d_in[7];
    const float* g2b  = (const float*)d_in[8];
    const float* outw = (const float*)d_in[9];
    const float* outb = (const float*)d_in[10];

    cudaFuncSetAttribute(node_kernel,
                         cudaFuncAttributeMaxDynamicSharedMemorySize, SMEM_BYTES);

    prep_kernel<<<16, 256>>>(h2w, g2w);
    node_kernel<<<GRID, THREADS, SMEM_BYTES>>>(x0, h1w, h1b, g1w, g1b,
                                               h2b, g2b, outw, outb,
                                               (float*)d_out);
}